// round 5
// baseline (speedup 1.0000x reference)
#include <cuda_runtime.h>
#include <math.h>
#include <stdint.h>

#define B_    32
#define T_    500
#define DENC  512
#define H_    1024
#define EMB   512
#define ODIM  5000
#define ATT   512
#define LY    128
#define NSTEP 129
#define EOSx  4999
#define GRID  148
#define TPB   256

// ---------------- device scratch (static, allocation-free) ----------------
__device__ __align__(256) float g_pre[B_ * T_ * ATT];
__device__ __align__(256) float g_WencT[ATT * DENC];
__device__ __align__(256) float g_WdecT[ATT * H_];
__device__ __align__(256) float g_dec[B_ * ATT];
__device__ __align__(256) float g_e[B_ * T_];
__device__ __align__(256) float g_xcat[B_ * (DENC + EMB)];
__device__ __align__(256) float g_h0[2][B_ * H_];
__device__ __align__(256) float g_h1[2][B_ * H_];
__device__ __align__(256) float g_c0[B_ * H_];
__device__ __align__(256) float g_c1[B_ * H_];
__device__ unsigned g_barcnt;
__device__ unsigned g_bargen;

// ---- fast fp32 tanh: rational P13/Q6 (Eigen ptanh), 1 MUFU via __fdividef
__device__ __forceinline__ float tanh_f(float x) {
    x = fmaxf(-7.99f, fminf(7.99f, x));
    float x2 = x * x;
    float p = fmaf(x2, -2.76076847742355e-16f, 2.00018790482477e-13f);
    p = fmaf(p, x2, -8.60467152213735e-11f);
    p = fmaf(p, x2, 5.12229709037114e-08f);
    p = fmaf(p, x2, 1.48572235717979e-05f);
    p = fmaf(p, x2, 6.37261928875436e-04f);
    p = fmaf(p, x2, 4.89352455891786e-03f);
    p *= x;
    float q = fmaf(x2, 1.19825839466702e-06f, 1.18534705686654e-04f);
    q = fmaf(q, x2, 2.26843463243900e-03f);
    q = fmaf(q, x2, 4.89352518554385e-03f);
    return __fdividef(p, q);
}
__device__ __forceinline__ float sigm_f(float x) {
    return fmaf(0.5f, tanh_f(0.5f * x), 0.5f);
}

// ---------------- cp.async helpers ----------------------------------------
__device__ __forceinline__ void cp16(uint32_t s, const float* g) {
    asm volatile("cp.async.cg.shared.global [%0], [%1], 16;" :: "r"(s), "l"(g));
}
__device__ __forceinline__ void cp_commit() { asm volatile("cp.async.commit_group;"); }
template<int N> __device__ __forceinline__ void cp_wait() {
    asm volatile("cp.async.wait_group %0;" :: "n"(N));
}

// ---------------- software grid barrier (persistent kernel) ---------------
__device__ __forceinline__ void gridbar() {
    __syncthreads();
    if (threadIdx.x == 0) {
        volatile unsigned* vgen = &g_bargen;
        __threadfence();                       // flush my writes
        unsigned gen = *vgen;
        unsigned a = atomicAdd(&g_barcnt, 1u);
        if (a == GRID - 1) {
            g_barcnt = 0;
            __threadfence();
            *vgen = gen + 1;                   // release
        } else {
            while (*vgen == gen) __nanosleep(64);
        }
        __threadfence();                       // reader-side visibility
    }
    __syncthreads();
}

// smem layout (floats): xs[2] @ 0 / 4224, ws[2] @ 8448 / 13568; total 18688
#define XS_OFF 0
#define XS_STR 4224
#define WS_OFF 8448
#define WS_STR 5120
#define SMEM_FLOATS 18688

// ---------------- GEMM core: 5 accs/warp, linear rows (dec + logits) ------
__device__ void gemm_lin5(const float* __restrict__ W, const float* __restrict__ x,
                          int K, int n0, int N, const float* __restrict__ bias,
                          float* __restrict__ outb, int ostride, float* smem) {
    int tid = threadIdx.x, warp = tid >> 5, lane = tid & 31;
    const int NKT = K >> 7;
    uint32_t sbase = (uint32_t)__cvta_generic_to_shared(smem);
    auto stageK = [&](int kt, int p) {
        int koff = kt << 7;
        uint32_t xb = sbase + (XS_OFF + p * XS_STR) * 4;
        uint32_t wb = sbase + (WS_OFF + p * WS_STR) * 4;
        #pragma unroll
        for (int u = 0; u < 4; u++) {
            int f = tid + u * 256; int m = f >> 5, kq = f & 31;
            cp16(xb + (m * 132 + kq * 4) * 4, x + m * K + koff + kq * 4);
        }
        #pragma unroll
        for (int u = 0; u < 5; u++) {
            int f = tid + u * 256; int n = f >> 5, kq = f & 31;
            int gr = n0 + n; if (gr >= N) gr = N - 1;
            cp16(wb + (n * 128 + kq * 4) * 4, W + (size_t)gr * K + koff + kq * 4);
        }
        cp_commit();
    };
    float a0 = 0.f, a1 = 0.f, a2 = 0.f, a3 = 0.f, a4 = 0.f;
    stageK(0, 0);
    for (int kt = 0; kt < NKT; kt++) {
        int p = kt & 1;
        if (kt + 1 < NKT) { stageK(kt + 1, p ^ 1); cp_wait<1>(); } else cp_wait<0>();
        __syncthreads();
        const float* xp = smem + XS_OFF + p * XS_STR + lane * 132;
        const float* wp = smem + WS_OFF + p * WS_STR + warp * 5 * 128;
        #pragma unroll
        for (int kk = 0; kk < 128; kk += 4) {
            float4 xv = *(const float4*)(xp + kk);
            float4 w0 = *(const float4*)(wp + 0 * 128 + kk);
            float4 w1 = *(const float4*)(wp + 1 * 128 + kk);
            float4 w2 = *(const float4*)(wp + 2 * 128 + kk);
            float4 w3 = *(const float4*)(wp + 3 * 128 + kk);
            float4 w4 = *(const float4*)(wp + 4 * 128 + kk);
            a0 += xv.x * w0.x + xv.y * w0.y + xv.z * w0.z + xv.w * w0.w;
            a1 += xv.x * w1.x + xv.y * w1.y + xv.z * w1.z + xv.w * w1.w;
            a2 += xv.x * w2.x + xv.y * w2.y + xv.z * w2.z + xv.w * w2.w;
            a3 += xv.x * w3.x + xv.y * w3.y + xv.z * w3.z + xv.w * w3.w;
            a4 += xv.x * w4.x + xv.y * w4.y + xv.z * w4.z + xv.w * w4.w;
        }
        __syncthreads();
    }
    float acc[5] = {a0, a1, a2, a3, a4};
    #pragma unroll
    for (int j = 0; j < 5; j++) {
        int n = n0 + warp * 5 + j;
        if (n < N) outb[(size_t)lane * ostride + n] = acc[j] + (bias ? bias[n] : 0.f);
    }
}

// ---------------- GEMM core: 4 gates of one hidden unit; LSTM epilogue ----
__device__ void gemm_gates(const float* __restrict__ Wih, const float* __restrict__ Whh,
                           const float* __restrict__ xa, const float* __restrict__ xb,
                           int j0, const float* __restrict__ bih,
                           const float* __restrict__ bhh,
                           float* __restrict__ hout, float* __restrict__ c,
                           float* smem) {
    int tid = threadIdx.x, warp = tid >> 5, lane = tid & 31;
    const int NKT = 16;                       // K = 1024 + 1024
    uint32_t sbase = (uint32_t)__cvta_generic_to_shared(smem);
    auto stageK = [&](int kt, int p) {
        int koff = kt << 7;
        const float* xsrc = xa; const float* wsrc = Wih;
        if (koff >= 1024) { koff -= 1024; xsrc = xb; wsrc = Whh; }
        uint32_t xbuf = sbase + (XS_OFF + p * XS_STR) * 4;
        uint32_t wbuf = sbase + (WS_OFF + p * WS_STR) * 4;
        #pragma unroll
        for (int u = 0; u < 4; u++) {
            int f = tid + u * 256; int m = f >> 5, kq = f & 31;
            cp16(xbuf + (m * 132 + kq * 4) * 4, xsrc + m * 1024 + koff + kq * 4);
        }
        #pragma unroll
        for (int u = 0; u < 4; u++) {
            int f = tid + u * 256; int n = f >> 5, kq = f & 31;
            int grow = (n >> 3) * H_ + j0 + (n & 7);
            cp16(wbuf + (n * 128 + kq * 4) * 4, wsrc + (size_t)grow * 1024 + koff + kq * 4);
        }
        cp_commit();
    };
    float a0 = 0.f, a1 = 0.f, a2 = 0.f, a3 = 0.f;
    stageK(0, 0);
    for (int kt = 0; kt < NKT; kt++) {
        int p = kt & 1;
        if (kt + 1 < NKT) { stageK(kt + 1, p ^ 1); cp_wait<1>(); } else cp_wait<0>();
        __syncthreads();
        const float* xp = smem + XS_OFF + p * XS_STR + lane * 132;
        const float* wp = smem + WS_OFF + p * WS_STR + warp * 128;
        #pragma unroll
        for (int kk = 0; kk < 128; kk += 4) {
            float4 xv = *(const float4*)(xp + kk);
            float4 w0 = *(const float4*)(wp + 0 * 8 * 128 + kk);
            float4 w1 = *(const float4*)(wp + 1 * 8 * 128 + kk);
            float4 w2 = *(const float4*)(wp + 2 * 8 * 128 + kk);
            float4 w3 = *(const float4*)(wp + 3 * 8 * 128 + kk);
            a0 += xv.x * w0.x + xv.y * w0.y + xv.z * w0.z + xv.w * w0.w;
            a1 += xv.x * w1.x + xv.y * w1.y + xv.z * w1.z + xv.w * w1.w;
            a2 += xv.x * w2.x + xv.y * w2.y + xv.z * w2.z + xv.w * w2.w;
            a3 += xv.x * w3.x + xv.y * w3.y + xv.z * w3.z + xv.w * w3.w;
        }
        __syncthreads();
    }
    int j = j0 + warp;
    float gi = sigm_f(a0 + bih[j]          + bhh[j]);
    float gf = sigm_f(a1 + bih[H_ + j]     + bhh[H_ + j]);
    float gg = tanh_f(a2 + bih[2 * H_ + j] + bhh[2 * H_ + j]);
    float go = sigm_f(a3 + bih[3 * H_ + j] + bhh[3 * H_ + j]);
    int idx = lane * H_ + j;
    float cn = gf * c[idx] + gi * gg;
    c[idx] = cn;
    hout[idx] = go * tanh_f(cn);
}

// ---------------- persistent decoder kernel -------------------------------
__global__ __launch_bounds__(TPB, 1)
void speller_persistent(const float* __restrict__ hs, const int* __restrict__ hlens,
                        const int* __restrict__ ys_out, const float* __restrict__ embed_W,
                        const float* __restrict__ Wih, const float* __restrict__ Whh,
                        const float* __restrict__ bih, const float* __restrict__ bhh,
                        const float* __restrict__ v, const float* __restrict__ Wproj,
                        const float* __restrict__ bproj, float* __restrict__ out) {
    extern __shared__ float smem[];
    int tid = threadIdx.x, lane = tid & 31, warp = tid >> 5;

    for (int t = 0; t <= NSTEP; t++) {
        int par = t & 1;
        const float* h0in  = g_h0[par];
        float*       h0out = g_h0[par ^ 1];
        const float* h1in  = g_h1[par];
        float*       h1out = g_h1[par ^ 1];

        // ---- stage X: logits(t-1) [t>=1] + dec(t) [t<=128] ----
        {
            int nlog = (t >= 1) ? 125 : 0;               // 125*40 = 5000
            int ndec = (t <= NSTEP - 1) ? 13 : 0;        // 13*40 covers 512
            for (int w = blockIdx.x; w < nlog + ndec; w += GRID) {
                if (w < nlog)
                    gemm_lin5(Wproj, h1in, 1024, w * 40, ODIM, bproj,
                              out + (size_t)(t - 1) * ODIM, NSTEP * ODIM, smem);
                else
                    gemm_lin5(g_WdecT, h0in, 1024, (w - nlog) * 40, ATT, nullptr,
                              g_dec, ATT, smem);
            }
        }
        if (t == NSTEP) break;
        gridbar();

        // ---- stage E: e[b,tau] = v . tanh(pre + dec), hlen-masked ----
        for (int u = blockIdx.x; u < B_ * 63; u += GRID) {
            int b = u / 63, ch = u - b * 63;
            int tau = ch * 8 + warp;
            if (tau < T_) {
                if (tau < hlens[b]) {
                    const float4* p4 = (const float4*)(g_pre + ((size_t)b * T_ + tau) * ATT);
                    const float4* d4 = (const float4*)(g_dec + b * ATT);
                    const float4* v4 = (const float4*)v;
                    float s = 0.f;
                    #pragma unroll
                    for (int a = lane; a < ATT / 4; a += 32) {
                        float4 pv = p4[a]; float4 dv = d4[a]; float4 vv = v4[a];
                        s += vv.x * tanh_f(pv.x + dv.x) + vv.y * tanh_f(pv.y + dv.y)
                           + vv.z * tanh_f(pv.z + dv.z) + vv.w * tanh_f(pv.w + dv.w);
                    }
                    #pragma unroll
                    for (int o = 16; o; o >>= 1) s += __shfl_xor_sync(0xffffffffu, s, o);
                    if (lane == 0) g_e[b * T_ + tau] = s;
                } else if (lane == 0) {
                    g_e[b * T_ + tau] = -1e9f;
                }
            }
        }
        gridbar();

        // ---- stage S: softmax + context + embedding (32 blocks) ----
        if (blockIdx.x < B_) {
            int b = blockIdx.x;
            int hl = hlens[b];
            float* wsm = smem;                 // [512]
            float* red = smem + 512;           // [8]
            float* bc  = smem + 520;
            float x0 = (tid < T_) ? g_e[b * T_ + tid] : -INFINITY;
            float x1 = (tid + 256 < T_) ? g_e[b * T_ + tid + 256] : -INFINITY;
            float m = fmaxf(x0, x1);
            #pragma unroll
            for (int o = 16; o; o >>= 1) m = fmaxf(m, __shfl_xor_sync(0xffffffffu, m, o));
            if (lane == 0) red[warp] = m;
            __syncthreads();
            if (tid == 0) {
                float mm = red[0];
                #pragma unroll
                for (int i = 1; i < 8; i++) mm = fmaxf(mm, red[i]);
                bc[0] = mm;
            }
            __syncthreads();
            float mx = bc[0];
            float p0 = (tid < T_) ? __expf(x0 - mx) : 0.f;
            float p1 = (tid + 256 < T_) ? __expf(x1 - mx) : 0.f;
            float s = p0 + p1;
            #pragma unroll
            for (int o = 16; o; o >>= 1) s += __shfl_xor_sync(0xffffffffu, s, o);
            __syncthreads();
            if (lane == 0) red[warp] = s;
            __syncthreads();
            if (tid == 0) {
                float ss = 0.f;
                #pragma unroll
                for (int i = 0; i < 8; i++) ss += red[i];
                bc[1] = 1.f / ss;
            }
            __syncthreads();
            float inv = bc[1];
            if (tid < T_) wsm[tid] = p0 * inv;
            if (tid + 256 < T_) wsm[tid + 256] = p1 * inv;
            __syncthreads();
            // ctx over tau < hl only (weights are exactly 0 beyond hl)
            const float2* hp = (const float2*)(hs + (size_t)b * T_ * DENC);
            float2 acc0 = {0.f, 0.f}, acc1 = {0.f, 0.f};
            int hl2 = hl & ~1;
            for (int tau = 0; tau < hl2; tau += 2) {
                float w0 = wsm[tau], w1 = wsm[tau + 1];
                float2 h0v = hp[(size_t)tau * 256 + tid];
                float2 h1v = hp[(size_t)(tau + 1) * 256 + tid];
                acc0.x += w0 * h0v.x; acc0.y += w0 * h0v.y;
                acc1.x += w1 * h1v.x; acc1.y += w1 * h1v.y;
            }
            if (hl & 1) {
                float w0 = wsm[hl2];
                float2 h0v = hp[(size_t)hl2 * 256 + tid];
                acc0.x += w0 * h0v.x; acc0.y += w0 * h0v.y;
            }
            float2 ctx = {acc0.x + acc1.x, acc0.y + acc1.y};
            ((float2*)(g_xcat + b * (DENC + EMB)))[tid] = ctx;
            int tok;
            if (t == 0) tok = EOSx;
            else { tok = ys_out[b * LY + (t - 1)]; if (tok < 0) tok = EOSx; }
            float2 ev = ((const float2*)(embed_W + (size_t)tok * EMB))[tid];
            ((float2*)(g_xcat + b * (DENC + EMB) + DENC))[tid] = ev;
        }
        gridbar();

        // ---- stage L0 ----
        for (int w = blockIdx.x; w < 128; w += GRID)
            gemm_gates(Wih, Whh, g_xcat, h0in, w * 8, bih, bhh, h0out, g_c0, smem);
        gridbar();

        // ---- stage L1 ----
        for (int w = blockIdx.x; w < 128; w += GRID)
            gemm_gates(Wih + (size_t)4 * H_ * H_, Whh + (size_t)4 * H_ * H_,
                       h0out, h1in, w * 8, bih + 4 * H_, bhh + 4 * H_,
                       h1out, g_c1, smem);
        gridbar();
    }
}

// ---------------- setup: zero state + barrier, write ys_ref tail ----------
__global__ void setup_kernel(const int* __restrict__ ys_out, float* __restrict__ out,
                             long long out_size) {
    int i = blockIdx.x * 256 + threadIdx.x;
    if (i == 0) { g_barcnt = 0; g_bargen = 0; }
    if (i < B_ * H_) {
        g_h0[0][i] = 0.f; g_h0[1][i] = 0.f;
        g_h1[0][i] = 0.f; g_h1[1][i] = 0.f;
        g_c0[i] = 0.f; g_c1[i] = 0.f;
    }
    const long long LOGITS = (long long)B_ * NSTEP * ODIM;
    if (i < B_ * NSTEP && out_size >= LOGITS + B_ * NSTEP) {
        int b = i / NSTEP, p = i % NSTEP;
        float vv = (p < LY) ? (float)ys_out[b * LY + p] : (float)EOSx;
        out[LOGITS + i] = vv;
    }
}

// ---------------- transpose (Wenc, Wdec -> N-major) ------------------------
__global__ void transpose_kernel(const float* __restrict__ in, float* __restrict__ out,
                                 int R, int C) {
    __shared__ float tile[32][33];
    int c = blockIdx.x * 32 + threadIdx.x;
    int r0 = blockIdx.y * 32;
    for (int i = threadIdx.y; i < 32; i += 8) {
        int r = r0 + i;
        if (r < R && c < C) tile[i][threadIdx.x] = in[r * C + c];
    }
    __syncthreads();
    int c2 = r0 + threadIdx.x;
    int r2 = blockIdx.x * 32;
    for (int i = threadIdx.y; i < 32; i += 8) {
        int rr = r2 + i;
        if (rr < C && c2 < R) out[rr * R + c2] = tile[threadIdx.x][i];
    }
}

// ---------------- one-time encoder projection GEMM -------------------------
__global__ __launch_bounds__(256)
void pre_gemm_kernel(const float* __restrict__ W, const float* __restrict__ x,
                     float* __restrict__ outp) {
    __shared__ __align__(16) float xs[32 * 132];
    __shared__ __align__(16) float ws[32 * 128];
    int tid = threadIdx.x, warp = tid >> 5, lane = tid & 31;
    int n0 = blockIdx.x * 32, mbase = blockIdx.y * 32;
    float a0 = 0.f, a1 = 0.f, a2 = 0.f, a3 = 0.f;
    for (int kt = 0; kt < DENC; kt += 128) {
        #pragma unroll
        for (int i = tid; i < 32 * 128; i += 256) {
            int m = i >> 7, k = i & 127;
            xs[m * 132 + k] = x[(size_t)(mbase + m) * DENC + kt + k];
            ws[i] = W[(size_t)(n0 + m) * DENC + kt + k];
        }
        __syncthreads();
        const float* wp = &ws[(warp * 4) * 128];
        const float* xp = &xs[lane * 132];
        #pragma unroll
        for (int kk = 0; kk < 128; kk += 4) {
            float4 xv = *(const float4*)(xp + kk);
            float4 w0 = *(const float4*)(wp + 0 * 128 + kk);
            float4 w1 = *(const float4*)(wp + 1 * 128 + kk);
            float4 w2 = *(const float4*)(wp + 2 * 128 + kk);
            float4 w3 = *(const float4*)(wp + 3 * 128 + kk);
            a0 += xv.x * w0.x + xv.y * w0.y + xv.z * w0.z + xv.w * w0.w;
            a1 += xv.x * w1.x + xv.y * w1.y + xv.z * w1.z + xv.w * w1.w;
            a2 += xv.x * w2.x + xv.y * w2.y + xv.z * w2.z + xv.w * w2.w;
            a3 += xv.x * w3.x + xv.y * w3.y + xv.z * w3.z + xv.w * w3.w;
        }
        __syncthreads();
    }
    float acc[4] = {a0, a1, a2, a3};
    #pragma unroll
    for (int j = 0; j < 4; j++)
        outp[(size_t)(mbase + lane) * ATT + n0 + warp * 4 + j] = acc[j];
}

// --------------------------------------------------------------------------
extern "C" void kernel_launch(void* const* d_in, const int* in_sizes, int n_in,
                              void* d_out, int out_size) {
    const float* hs      = (const float*)d_in[0];
    const int*   hlens   = (const int*)  d_in[1];
    const int*   ys_out  = (const int*)  d_in[2];
    const float* embed_W = (const float*)d_in[3];
    const float* Wih     = (const float*)d_in[4];
    const float* Whh     = (const float*)d_in[5];
    const float* bih     = (const float*)d_in[6];
    const float* bhh     = (const float*)d_in[7];
    const float* Wenc    = (const float*)d_in[8];
    const float* Wdec    = (const float*)d_in[9];
    const float* v       = (const float*)d_in[10];
    const float* Wproj   = (const float*)d_in[11];
    const float* bproj   = (const float*)d_in[12];
    float* out = (float*)d_out;

    float *p_WencT, *p_WdecT, *p_pre;
    cudaGetSymbolAddress((void**)&p_WencT, g_WencT);
    cudaGetSymbolAddress((void**)&p_WdecT, g_WdecT);
    cudaGetSymbolAddress((void**)&p_pre,   g_pre);

    cudaFuncSetAttribute(speller_persistent,
                         cudaFuncAttributeMaxDynamicSharedMemorySize,
                         SMEM_FLOATS * 4);

    setup_kernel<<<128, 256>>>(ys_out, out, (long long)out_size);
    transpose_kernel<<<dim3(16, 16), dim3(32, 8)>>>(Wenc, p_WencT, DENC, ATT);
    transpose_kernel<<<dim3(16, 32), dim3(32, 8)>>>(Wdec, p_WdecT, H_, ATT);
    pre_gemm_kernel<<<dim3(ATT / 32, 500), 256>>>(p_WencT, hs, p_pre);
    speller_persistent<<<GRID, TPB, SMEM_FLOATS * 4>>>(
        hs, hlens, ys_out, embed_W, Wih, Whh, bih, bhh, v, Wproj, bproj, out);
}

// round 6
// speedup vs baseline: 1.0150x; 1.0150x over previous
#include <cuda_runtime.h>
#include <math.h>
#include <stdint.h>

#define B_    32
#define T_    500
#define DENC  512
#define H_    1024
#define EMB   512
#define ODIM  5000
#define ATT   512
#define LY    128
#define NSTEP 129
#define EOSx  4999
#define GRID  148
#define TPB   256

typedef unsigned long long u64;

// ---------------- device scratch (static, allocation-free) ----------------
__device__ __align__(256) float g_pre[B_ * T_ * ATT];
__device__ __align__(256) float g_WencT[ATT * DENC];
__device__ __align__(256) float g_WdecT[ATT * H_];
__device__ __align__(256) float g_dec[B_ * ATT];
__device__ __align__(256) float g_e[B_ * T_];
__device__ __align__(256) float g_xcat[B_ * (DENC + EMB)];
__device__ __align__(256) float g_h0[2][B_ * H_];
__device__ __align__(256) float g_h1[2][B_ * H_];
__device__ __align__(256) float g_c0[B_ * H_];
__device__ __align__(256) float g_c1[B_ * H_];
__device__ unsigned g_barcnt;
__device__ unsigned g_bargen;

// ---- packed fp32x2 FMA (Blackwell; ptxas never auto-fuses this) ----------
__device__ __forceinline__ void ffma2(u64& d, u64 a, u64 b) {
    asm("fma.rn.f32x2 %0, %1, %2, %0;" : "+l"(d) : "l"(a), "l"(b));
}
__device__ __forceinline__ float hadd2(u64 d) {
    float lo = __int_as_float((unsigned)(d & 0xffffffffu));
    float hi = __int_as_float((unsigned)(d >> 32));
    return lo + hi;
}

// ---- fast fp32 tanh: rational P13/Q6 (Eigen ptanh), 1 MUFU via __fdividef
__device__ __forceinline__ float tanh_f(float x) {
    x = fmaxf(-7.99f, fminf(7.99f, x));
    float x2 = x * x;
    float p = fmaf(x2, -2.76076847742355e-16f, 2.00018790482477e-13f);
    p = fmaf(p, x2, -8.60467152213735e-11f);
    p = fmaf(p, x2, 5.12229709037114e-08f);
    p = fmaf(p, x2, 1.48572235717979e-05f);
    p = fmaf(p, x2, 6.37261928875436e-04f);
    p = fmaf(p, x2, 4.89352455891786e-03f);
    p *= x;
    float q = fmaf(x2, 1.19825839466702e-06f, 1.18534705686654e-04f);
    q = fmaf(q, x2, 2.26843463243900e-03f);
    q = fmaf(q, x2, 4.89352518554385e-03f);
    return __fdividef(p, q);
}
__device__ __forceinline__ float sigm_f(float x) {
    return fmaf(0.5f, tanh_f(0.5f * x), 0.5f);
}

// ---------------- cp.async helpers ----------------------------------------
__device__ __forceinline__ void cp16(uint32_t s, const float* g) {
    asm volatile("cp.async.cg.shared.global [%0], [%1], 16;" :: "r"(s), "l"(g));
}
__device__ __forceinline__ void cp_commit() { asm volatile("cp.async.commit_group;"); }
template<int N> __device__ __forceinline__ void cp_wait() {
    asm volatile("cp.async.wait_group %0;" :: "n"(N));
}

// ---------------- software grid barrier (persistent kernel) ---------------
__device__ __forceinline__ void gridbar() {
    __syncthreads();
    if (threadIdx.x == 0) {
        volatile unsigned* vgen = &g_bargen;
        __threadfence();
        unsigned gen = *vgen;
        unsigned a = atomicAdd(&g_barcnt, 1u);
        if (a == GRID - 1) {
            g_barcnt = 0;
            __threadfence();
            *vgen = gen + 1;
        } else {
            while (*vgen == gen) __nanosleep(64);
        }
        __threadfence();
    }
    __syncthreads();
}

// smem layout (floats): xs[2] @ 0 / 4224, ws[2] @ 8448 / 13568; total 18688
#define XS_OFF 0
#define XS_STR 4224
#define WS_OFF 8448
#define WS_STR 5120
#define SMEM_FLOATS 18688

// ---------------- GEMM core: 5 accs/warp, linear rows (dec + logits) ------
__device__ void gemm_lin5(const float* __restrict__ W, const float* __restrict__ x,
                          int K, int n0, int N, const float* __restrict__ bias,
                          float* __restrict__ outb, int ostride, float* smem) {
    int tid = threadIdx.x, warp = tid >> 5, lane = tid & 31;
    const int NKT = K >> 7;
    uint32_t sbase = (uint32_t)__cvta_generic_to_shared(smem);
    auto stageK = [&](int kt, int p) {
        int koff = kt << 7;
        uint32_t xb = sbase + (XS_OFF + p * XS_STR) * 4;
        uint32_t wb = sbase + (WS_OFF + p * WS_STR) * 4;
        #pragma unroll
        for (int u = 0; u < 4; u++) {
            int f = tid + u * 256; int m = f >> 5, kq = f & 31;
            cp16(xb + (m * 132 + kq * 4) * 4, x + m * K + koff + kq * 4);
        }
        #pragma unroll
        for (int u = 0; u < 5; u++) {
            int f = tid + u * 256; int n = f >> 5, kq = f & 31;
            int gr = n0 + n; if (gr >= N) gr = N - 1;
            cp16(wb + (n * 128 + kq * 4) * 4, W + (size_t)gr * K + koff + kq * 4);
        }
        cp_commit();
    };
    u64 a0 = 0, a1 = 0, a2 = 0, a3 = 0, a4 = 0;
    stageK(0, 0);
    for (int kt = 0; kt < NKT; kt++) {
        int p = kt & 1;
        if (kt + 1 < NKT) { stageK(kt + 1, p ^ 1); cp_wait<1>(); } else cp_wait<0>();
        __syncthreads();
        const ulonglong2* xp = (const ulonglong2*)(smem + XS_OFF + p * XS_STR + lane * 132);
        const ulonglong2* wp = (const ulonglong2*)(smem + WS_OFF + p * WS_STR + warp * 5 * 128);
        #pragma unroll
        for (int q = 0; q < 32; q++) {           // 32 × (4 floats) = 128 k
            ulonglong2 xv = xp[q];
            ulonglong2 w0 = wp[q];
            ulonglong2 w1 = wp[32 + q];
            ulonglong2 w2 = wp[64 + q];
            ulonglong2 w3 = wp[96 + q];
            ulonglong2 w4 = wp[128 + q];
            ffma2(a0, xv.x, w0.x); ffma2(a0, xv.y, w0.y);
            ffma2(a1, xv.x, w1.x); ffma2(a1, xv.y, w1.y);
            ffma2(a2, xv.x, w2.x); ffma2(a2, xv.y, w2.y);
            ffma2(a3, xv.x, w3.x); ffma2(a3, xv.y, w3.y);
            ffma2(a4, xv.x, w4.x); ffma2(a4, xv.y, w4.y);
        }
        __syncthreads();
    }
    float acc[5] = {hadd2(a0), hadd2(a1), hadd2(a2), hadd2(a3), hadd2(a4)};
    #pragma unroll
    for (int j = 0; j < 5; j++) {
        int n = n0 + warp * 5 + j;
        if (n < N) outb[(size_t)lane * ostride + n] = acc[j] + (bias ? bias[n] : 0.f);
    }
}

// ---------------- GEMM core: 4 gates of one hidden unit; LSTM epilogue ----
__device__ void gemm_gates(const float* __restrict__ Wih, const float* __restrict__ Whh,
                           const float* __restrict__ xa, const float* __restrict__ xb,
                           int j0, const float* __restrict__ bih,
                           const float* __restrict__ bhh,
                           float* __restrict__ hout, float* __restrict__ c,
                           float* smem) {
    int tid = threadIdx.x, warp = tid >> 5, lane = tid & 31;
    const int NKT = 16;                       // K = 1024 + 1024
    uint32_t sbase = (uint32_t)__cvta_generic_to_shared(smem);
    auto stageK = [&](int kt, int p) {
        int koff = kt << 7;
        const float* xsrc = xa; const float* wsrc = Wih;
        if (koff >= 1024) { koff -= 1024; xsrc = xb; wsrc = Whh; }
        uint32_t xbuf = sbase + (XS_OFF + p * XS_STR) * 4;
        uint32_t wbuf = sbase + (WS_OFF + p * WS_STR) * 4;
        #pragma unroll
        for (int u = 0; u < 4; u++) {
            int f = tid + u * 256; int m = f >> 5, kq = f & 31;
            cp16(xbuf + (m * 132 + kq * 4) * 4, xsrc + m * 1024 + koff + kq * 4);
        }
        #pragma unroll
        for (int u = 0; u < 4; u++) {
            int f = tid + u * 256; int n = f >> 5, kq = f & 31;
            int grow = (n >> 3) * H_ + j0 + (n & 7);
            cp16(wbuf + (n * 128 + kq * 4) * 4, wsrc + (size_t)grow * 1024 + koff + kq * 4);
        }
        cp_commit();
    };
    u64 a0 = 0, a1 = 0, a2 = 0, a3 = 0;
    stageK(0, 0);
    for (int kt = 0; kt < NKT; kt++) {
        int p = kt & 1;
        if (kt + 1 < NKT) { stageK(kt + 1, p ^ 1); cp_wait<1>(); } else cp_wait<0>();
        __syncthreads();
        const ulonglong2* xp = (const ulonglong2*)(smem + XS_OFF + p * XS_STR + lane * 132);
        const ulonglong2* wp = (const ulonglong2*)(smem + WS_OFF + p * WS_STR + warp * 128);
        #pragma unroll
        for (int q = 0; q < 32; q++) {
            ulonglong2 xv = xp[q];
            ulonglong2 w0 = wp[0 * 8 * 32 + q];
            ulonglong2 w1 = wp[1 * 8 * 32 + q];
            ulonglong2 w2 = wp[2 * 8 * 32 + q];
            ulonglong2 w3 = wp[3 * 8 * 32 + q];
            ffma2(a0, xv.x, w0.x); ffma2(a0, xv.y, w0.y);
            ffma2(a1, xv.x, w1.x); ffma2(a1, xv.y, w1.y);
            ffma2(a2, xv.x, w2.x); ffma2(a2, xv.y, w2.y);
            ffma2(a3, xv.x, w3.x); ffma2(a3, xv.y, w3.y);
        }
        __syncthreads();
    }
    int j = j0 + warp;
    float gi = sigm_f(hadd2(a0) + bih[j]          + bhh[j]);
    float gf = sigm_f(hadd2(a1) + bih[H_ + j]     + bhh[H_ + j]);
    float gg = tanh_f(hadd2(a2) + bih[2 * H_ + j] + bhh[2 * H_ + j]);
    float go = sigm_f(hadd2(a3) + bih[3 * H_ + j] + bhh[3 * H_ + j]);
    int idx = lane * H_ + j;
    float cn = gf * c[idx] + gi * gg;
    c[idx] = cn;
    hout[idx] = go * tanh_f(cn);
}

// ---------------- persistent decoder kernel -------------------------------
__global__ __launch_bounds__(TPB, 1)
void speller_persistent(const float* __restrict__ hs, const int* __restrict__ hlens,
                        const int* __restrict__ ys_out, const float* __restrict__ embed_W,
                        const float* __restrict__ Wih, const float* __restrict__ Whh,
                        const float* __restrict__ bih, const float* __restrict__ bhh,
                        const float* __restrict__ v, const float* __restrict__ Wproj,
                        const float* __restrict__ bproj, float* __restrict__ out) {
    extern __shared__ float smem[];
    int tid = threadIdx.x, lane = tid & 31, warp = tid >> 5;

    for (int t = 0; t <= NSTEP; t++) {
        int par = t & 1;
        const float* h0in  = g_h0[par];
        float*       h0out = g_h0[par ^ 1];
        const float* h1in  = g_h1[par];
        float*       h1out = g_h1[par ^ 1];

        // ---- stage X: logits(t-1) [t>=1] + dec(t) [t<=128] ----
        {
            int nlog = (t >= 1) ? 125 : 0;               // 125*40 = 5000
            int ndec = (t <= NSTEP - 1) ? 13 : 0;        // 13*40 covers 512
            for (int w = blockIdx.x; w < nlog + ndec; w += GRID) {
                if (w < nlog)
                    gemm_lin5(Wproj, h1in, 1024, w * 40, ODIM, bproj,
                              out + (size_t)(t - 1) * ODIM, NSTEP * ODIM, smem);
                else
                    gemm_lin5(g_WdecT, h0in, 1024, (w - nlog) * 40, ATT, nullptr,
                              g_dec, ATT, smem);
            }
        }
        if (t == NSTEP) break;
        gridbar();

        // ---- stage E: e[b,tau] = v . tanh(pre + dec), hlen-masked ----
        for (int u = blockIdx.x; u < B_ * 63; u += GRID) {
            int b = u / 63, ch = u - b * 63;
            int tau = ch * 8 + warp;
            if (tau < T_) {
                if (tau < hlens[b]) {
                    const float4* p4 = (const float4*)(g_pre + ((size_t)b * T_ + tau) * ATT);
                    const float4* d4 = (const float4*)(g_dec + b * ATT);
                    const float4* v4 = (const float4*)v;
                    float s = 0.f;
                    #pragma unroll
                    for (int a = lane; a < ATT / 4; a += 32) {
                        float4 pv = p4[a]; float4 dv = d4[a]; float4 vv = v4[a];
                        s += vv.x * tanh_f(pv.x + dv.x) + vv.y * tanh_f(pv.y + dv.y)
                           + vv.z * tanh_f(pv.z + dv.z) + vv.w * tanh_f(pv.w + dv.w);
                    }
                    #pragma unroll
                    for (int o = 16; o; o >>= 1) s += __shfl_xor_sync(0xffffffffu, s, o);
                    if (lane == 0) g_e[b * T_ + tau] = s;
                } else if (lane == 0) {
                    g_e[b * T_ + tau] = -1e9f;
                }
            }
        }
        gridbar();

        // ---- stage S: softmax + context + embedding (32 blocks) ----
        if (blockIdx.x < B_) {
            int b = blockIdx.x;
            int hl = hlens[b];
            float* wsm = smem;                 // [512]
            float* red = smem + 512;           // [8]
            float* bc  = smem + 520;
            float x0 = (tid < T_) ? g_e[b * T_ + tid] : -INFINITY;
            float x1 = (tid + 256 < T_) ? g_e[b * T_ + tid + 256] : -INFINITY;
            float m = fmaxf(x0, x1);
            #pragma unroll
            for (int o = 16; o; o >>= 1) m = fmaxf(m, __shfl_xor_sync(0xffffffffu, m, o));
            if (lane == 0) red[warp] = m;
            __syncthreads();
            if (tid == 0) {
                float mm = red[0];
                #pragma unroll
                for (int i = 1; i < 8; i++) mm = fmaxf(mm, red[i]);
                bc[0] = mm;
            }
            __syncthreads();
            float mx = bc[0];
            float p0 = (tid < T_) ? __expf(x0 - mx) : 0.f;
            float p1 = (tid + 256 < T_) ? __expf(x1 - mx) : 0.f;
            float s = p0 + p1;
            #pragma unroll
            for (int o = 16; o; o >>= 1) s += __shfl_xor_sync(0xffffffffu, s, o);
            __syncthreads();
            if (lane == 0) red[warp] = s;
            __syncthreads();
            if (tid == 0) {
                float ss = 0.f;
                #pragma unroll
                for (int i = 0; i < 8; i++) ss += red[i];
                bc[1] = 1.f / ss;
            }
            __syncthreads();
            float inv = bc[1];
            if (tid < T_) wsm[tid] = p0 * inv;
            if (tid + 256 < T_) wsm[tid + 256] = p1 * inv;
            __syncthreads();
            const float2* hp = (const float2*)(hs + (size_t)b * T_ * DENC);
            float2 acc0 = {0.f, 0.f}, acc1 = {0.f, 0.f};
            int hl2 = hl & ~1;
            for (int tau = 0; tau < hl2; tau += 2) {
                float w0 = wsm[tau], w1 = wsm[tau + 1];
                float2 h0v = hp[(size_t)tau * 256 + tid];
                float2 h1v = hp[(size_t)(tau + 1) * 256 + tid];
                acc0.x += w0 * h0v.x; acc0.y += w0 * h0v.y;
                acc1.x += w1 * h1v.x; acc1.y += w1 * h1v.y;
            }
            if (hl & 1) {
                float w0 = wsm[hl2];
                float2 h0v = hp[(size_t)hl2 * 256 + tid];
                acc0.x += w0 * h0v.x; acc0.y += w0 * h0v.y;
            }
            float2 ctx = {acc0.x + acc1.x, acc0.y + acc1.y};
            ((float2*)(g_xcat + b * (DENC + EMB)))[tid] = ctx;
            int tok;
            if (t == 0) tok = EOSx;
            else { tok = ys_out[b * LY + (t - 1)]; if (tok < 0) tok = EOSx; }
            float2 ev = ((const float2*)(embed_W + (size_t)tok * EMB))[tid];
            ((float2*)(g_xcat + b * (DENC + EMB) + DENC))[tid] = ev;
        }
        gridbar();

        // ---- stage L0 ----
        for (int w = blockIdx.x; w < 128; w += GRID)
            gemm_gates(Wih, Whh, g_xcat, h0in, w * 8, bih, bhh, h0out, g_c0, smem);
        gridbar();

        // ---- stage L1 ----
        for (int w = blockIdx.x; w < 128; w += GRID)
            gemm_gates(Wih + (size_t)4 * H_ * H_, Whh + (size_t)4 * H_ * H_,
                       h0out, h1in, w * 8, bih + 4 * H_, bhh + 4 * H_,
                       h1out, g_c1, smem);
        gridbar();
    }
}

// ---------------- setup: zero state + barrier, write ys_ref tail ----------
__global__ void setup_kernel(const int* __restrict__ ys_out, float* __restrict__ out,
                             long long out_size) {
    int i = blockIdx.x * 256 + threadIdx.x;
    if (i == 0) { g_barcnt = 0; g_bargen = 0; }
    if (i < B_ * H_) {
        g_h0[0][i] = 0.f; g_h0[1][i] = 0.f;
        g_h1[0][i] = 0.f; g_h1[1][i] = 0.f;
        g_c0[i] = 0.f; g_c1[i] = 0.f;
    }
    const long long LOGITS = (long long)B_ * NSTEP * ODIM;
    if (i < B_ * NSTEP && out_size >= LOGITS + B_ * NSTEP) {
        int b = i / NSTEP, p = i % NSTEP;
        float vv = (p < LY) ? (float)ys_out[b * LY + p] : (float)EOSx;
        out[LOGITS + i] = vv;
    }
}

// ---------------- transpose (Wenc, Wdec -> N-major) ------------------------
__global__ void transpose_kernel(const float* __restrict__ in, float* __restrict__ out,
                                 int R, int C) {
    __shared__ float tile[32][33];
    int c = blockIdx.x * 32 + threadIdx.x;
    int r0 = blockIdx.y * 32;
    for (int i = threadIdx.y; i < 32; i += 8) {
        int r = r0 + i;
        if (r < R && c < C) tile[i][threadIdx.x] = in[r * C + c];
    }
    __syncthreads();
    int c2 = r0 + threadIdx.x;
    int r2 = blockIdx.x * 32;
    for (int i = threadIdx.y; i < 32; i += 8) {
        int rr = r2 + i;
        if (rr < C && c2 < R) out[rr * R + c2] = tile[threadIdx.x][i];
    }
}

// ---------------- one-time encoder projection GEMM -------------------------
__global__ __launch_bounds__(256)
void pre_gemm_kernel(const float* __restrict__ W, const float* __restrict__ x,
                     float* __restrict__ outp) {
    __shared__ __align__(16) float xs[32 * 132];
    __shared__ __align__(16) float ws[32 * 128];
    int tid = threadIdx.x, warp = tid >> 5, lane = tid & 31;
    int n0 = blockIdx.x * 32, mbase = blockIdx.y * 32;
    u64 a0 = 0, a1 = 0, a2 = 0, a3 = 0;
    for (int kt = 0; kt < DENC; kt += 128) {
        #pragma unroll
        for (int i = tid; i < 32 * 128; i += 256) {
            int m = i >> 7, k = i & 127;
            xs[m * 132 + k] = x[(size_t)(mbase + m) * DENC + kt + k];
            ws[i] = W[(size_t)(n0 + m) * DENC + kt + k];
        }
        __syncthreads();
        const ulonglong2* xp = (const ulonglong2*)(xs + lane * 132);
        const ulonglong2* wp = (const ulonglong2*)(ws + warp * 4 * 128);
        #pragma unroll
        for (int q = 0; q < 32; q++) {
            ulonglong2 xv = xp[q];
            ulonglong2 w0 = wp[q];
            ulonglong2 w1 = wp[32 + q];
            ulonglong2 w2 = wp[64 + q];
            ulonglong2 w3 = wp[96 + q];
            ffma2(a0, xv.x, w0.x); ffma2(a0, xv.y, w0.y);
            ffma2(a1, xv.x, w1.x); ffma2(a1, xv.y, w1.y);
            ffma2(a2, xv.x, w2.x); ffma2(a2, xv.y, w2.y);
            ffma2(a3, xv.x, w3.x); ffma2(a3, xv.y, w3.y);
        }
        __syncthreads();
    }
    float acc[4] = {hadd2(a0), hadd2(a1), hadd2(a2), hadd2(a3)};
    #pragma unroll
    for (int j = 0; j < 4; j++)
        outp[(size_t)(mbase + lane) * ATT + n0 + warp * 4 + j] = acc[j];
}

// --------------------------------------------------------------------------
extern "C" void kernel_launch(void* const* d_in, const int* in_sizes, int n_in,
                              void* d_out, int out_size) {
    const float* hs      = (const float*)d_in[0];
    const int*   hlens   = (const int*)  d_in[1];
    const int*   ys_out  = (const int*)  d_in[2];
    const float* embed_W = (const float*)d_in[3];
    const float* Wih     = (const float*)d_in[4];
    const float* Whh     = (const float*)d_in[5];
    const float* bih     = (const float*)d_in[6];
    const float* bhh     = (const float*)d_in[7];
    const float* Wenc    = (const float*)d_in[8];
    const float* Wdec    = (const float*)d_in[9];
    const float* v       = (const float*)d_in[10];
    const float* Wproj   = (const float*)d_in[11];
    const float* bproj   = (const float*)d_in[12];
    float* out = (float*)d_out;

    float *p_WencT, *p_WdecT, *p_pre;
    cudaGetSymbolAddress((void**)&p_WencT, g_WencT);
    cudaGetSymbolAddress((void**)&p_WdecT, g_WdecT);
    cudaGetSymbolAddress((void**)&p_pre,   g_pre);

    cudaFuncSetAttribute(speller_persistent,
                         cudaFuncAttributeMaxDynamicSharedMemorySize,
                         SMEM_FLOATS * 4);

    setup_kernel<<<128, 256>>>(ys_out, out, (long long)out_size);
    transpose_kernel<<<dim3(16, 16), dim3(32, 8)>>>(Wenc, p_WencT, DENC, ATT);
    transpose_kernel<<<dim3(16, 32), dim3(32, 8)>>>(Wdec, p_WdecT, H_, ATT);
    pre_gemm_kernel<<<dim3(ATT / 32, 500), 256>>>(p_WencT, hs, p_pre);
    speller_persistent<<<GRID, TPB, SMEM_FLOATS * 4>>>(
        hs, hlens, ys_out, embed_W, Wih, Whh, bih, bhh, v, Wproj, bproj, out);
}